// round 1
// baseline (speedup 1.0000x reference)
#include <cuda_runtime.h>

// Problem constants (fixed by the dataset)
#define NBATCH 8192
#define NEL    16      // NUP + NDOWN
#define NSP    8       // NUP == NDOWN
#define NMO    32
#define NCONF  64

__device__ __forceinline__ float frcp(float x) {
    float r;
    asm("rcp.approx.f32 %0, %1;" : "=f"(r) : "f"(x));
    return r;
}

// Block = one batch. 512 threads = 64 configs x 8 lanes.
// Each 8-lane subgroup solves two 8x8 systems (up/down spin) via
// Gauss-Jordan with implicit partial pivoting, applying identical row ops
// to A and B so that tr(A^-1 B) is invariant. A ends as a permuted
// diagonal: tr = sum_k Bhat[p_k][k]/d_k, det = sign(pi) * prod d_k.
__global__ __launch_bounds__(512, 2)
void kinetic_kernel(const float* __restrict__ MO,
                    const float* __restrict__ d2MO,
                    const int*   __restrict__ cfg_up,
                    const int*   __restrict__ cfg_dn,
                    float*       __restrict__ out)
{
    __shared__ float sMO[NEL][NMO + 1];   // +1 pad: bank-conflict-free column gathers
    __shared__ float sD2[NEL][NMO + 1];
    __shared__ int   sUp[NCONF * NSP];
    __shared__ int   sDn[NCONF * NSP];

    const int b   = blockIdx.x;
    const int tid = threadIdx.x;

    // Stage this batch's MO/d2MO slice (16x32 each) + all configs.
    {
        const int e = tid >> 5;
        const int m = tid & 31;
        sMO[e][m] = MO[b * NEL * NMO + tid];
        sD2[e][m] = d2MO[b * NEL * NMO + tid];
        sUp[tid]  = cfg_up[tid];
        sDn[tid]  = cfg_dn[tid];
    }
    __syncthreads();

    const int c    = tid >> 3;       // config handled by this 8-lane group
    const int lr   = tid & 7;        // row index within the 8x8 matrix
    const int lane = tid & 31;       // lane within warp
    const int base = lane & 24;      // first lane of this subgroup (within warp)

    float trsum   = 0.0f;
    float detprod = 1.0f;

    #pragma unroll
    for (int spin = 0; spin < 2; spin++) {
        const int* cfg  = spin ? (sDn + c * NSP) : (sUp + c * NSP);
        const int  roff = spin ? NSP : 0;

        // Load my row of A and B: A[lr][j] = MO[b, lr+roff, cfg[j]]
        float a[8], bb[8];
        #pragma unroll
        for (int j = 0; j < 8; j++) {
            const int col = cfg[j];
            a[j]  = sMO[roff + lr][col];
            bb[j] = sD2[roff + lr][col];
        }

        // -------- Gauss-Jordan with implicit partial pivoting --------
        unsigned done = 0u;   // has my row been used as a pivot yet?
        int   kidx = 0;       // step at which my row pivoted
        float d    = 1.0f;    // my pivot value (diagonal entry of permuted diag)

        #pragma unroll
        for (int k = 0; k < 8; k++) {
            // argmax over unpivoted rows of |a[k]|, lane id packed in low bits
            unsigned u = done ? 0u
                : ((__float_as_uint(fabsf(a[k])) & 0xFFFFFFF8u) | (unsigned)lr);
            u = max(u, __shfl_xor_sync(0xffffffffu, u, 1));
            u = max(u, __shfl_xor_sync(0xffffffffu, u, 2));
            u = max(u, __shfl_xor_sync(0xffffffffu, u, 4));
            const int  pl  = (int)(u & 7u);
            const int  pa  = base + pl;          // absolute pivot lane in warp
            const bool isP = (lr == pl);

            const float piv = __shfl_sync(0xffffffffu, a[k], pa);
            const float r   = frcp(piv);
            const float m   = isP ? 0.0f : a[k] * r;

            if (isP) { d = a[k]; kidx = k; done = 1u; }

            // Eliminate column k in every other row; same op applied to B.
            #pragma unroll
            for (int j = 0; j < 8; j++) {
                const float pj = __shfl_sync(0xffffffffu, a[j], pa);
                a[j] = fmaf(-m, pj, a[j]);
            }
            #pragma unroll
            for (int j = 0; j < 8; j++) {
                const float qj = __shfl_sync(0xffffffffu, bb[j], pa);
                bb[j] = fmaf(-m, qj, bb[j]);
            }
        }

        // Trace contribution: Bhat[my_row][kidx] / d   (kidx is runtime -> sel chain)
        float bv = bb[0];
        #pragma unroll
        for (int j = 1; j < 8; j++) bv = (kidx == j) ? bb[j] : bv;
        float trc = bv * frcp(d);

        // Permutation sign via inversion count of (row -> pivot step).
        int inv = 0;
        #pragma unroll
        for (int off = 1; off < 8; off++) {
            const int s  = lr + off;
            const int ks = __shfl_sync(0xffffffffu, kidx, base + (s & 7));
            inv += (s < 8 && kidx > ks) ? 1 : 0;
        }
        float ds = (inv & 1) ? -d : d;   // fold per-lane parity into the product

        // Subgroup reductions: sum of traces, product of signed pivots.
        float tr  = trc;
        float det = ds;
        #pragma unroll
        for (int off = 1; off < 8; off <<= 1) {
            tr  += __shfl_xor_sync(0xffffffffu, tr,  off);
            det *= __shfl_xor_sync(0xffffffffu, det, off);
        }

        trsum   += tr;
        detprod *= det;
    }

    if (lr == 0) out[b * NCONF + c] = -0.5f * trsum * detprod;
}

extern "C" void kernel_launch(void* const* d_in, const int* in_sizes, int n_in,
                              void* d_out, int out_size)
{
    const float* MO     = (const float*)d_in[0];
    const float* d2MO   = (const float*)d_in[1];
    const int*   cfg_up = (const int*)d_in[2];
    const int*   cfg_dn = (const int*)d_in[3];
    float*       out    = (float*)d_out;

    kinetic_kernel<<<NBATCH, 512>>>(MO, d2MO, cfg_up, cfg_dn, out);
}

// round 2
// speedup vs baseline: 1.3803x; 1.3803x over previous
#include <cuda_runtime.h>

// Problem constants (fixed by the dataset)
#define NBATCH 8192
#define NEL    16      // NUP + NDOWN
#define NSP    8
#define NMO    32
#define NCONF  64

__device__ __forceinline__ float frcp(float x) {
    float r;
    asm("rcp.approx.f32 %0, %1;" : "=f"(r) : "f"(x));
    return r;
}

// Block = one batch, 256 threads = 64 configs x 4 lanes.
// Each 4-lane group solves two 8x8 systems (rows 2*ll and 2*ll+1 per lane)
// via Gauss-Jordan with implicit partial pivoting. Row ops applied to both
// A and B leave tr(A^-1 B) invariant; A ends as permuted diagonal:
//   tr = sum_k Bhat[p_k][k]/d_k,   det = sign(pi) * prod d_k.
// Pivot-row columns j<k are exactly dead at step k -> A broadcast/update
// restricted to j in [k,8).
__global__ __launch_bounds__(256, 3)
void kinetic_kernel(const float* __restrict__ MO,
                    const float* __restrict__ d2MO,
                    const int*   __restrict__ cfg_up,
                    const int*   __restrict__ cfg_dn,
                    float*       __restrict__ out)
{
    __shared__ float sMO[NEL][NMO + 1];   // +1 pad for conflict-free column gathers
    __shared__ float sD2[NEL][NMO + 1];
    __shared__ int   sUp[NCONF * NSP];
    __shared__ int   sDn[NCONF * NSP];

    const int b   = blockIdx.x;
    const int tid = threadIdx.x;

    #pragma unroll
    for (int i = 0; i < 2; i++) {
        const int t = tid + i * 256;
        sMO[t >> 5][t & 31] = MO[b * NEL * NMO + t];
        sD2[t >> 5][t & 31] = d2MO[b * NEL * NMO + t];
        sUp[t] = cfg_up[t];
        sDn[t] = cfg_dn[t];
    }
    __syncthreads();

    const int c    = tid >> 2;      // config 0..63
    const int ll   = tid & 3;       // lane within 4-lane group
    const int lane = tid & 31;
    const int base = lane & 28;     // first lane of this group in the warp
    const int row0 = 2 * ll;
    const int row1 = 2 * ll + 1;

    float trsum   = 0.0f;
    float detprod = 1.0f;

    #pragma unroll 1
    for (int spin = 0; spin < 2; spin++) {
        const int* cfg  = spin ? (sDn + c * NSP) : (sUp + c * NSP);
        const int  roff = spin ? NSP : 0;

        float a0[8], a1[8], b0[8], b1[8];
        #pragma unroll
        for (int j = 0; j < 8; j++) {
            const int col = cfg[j];
            a0[j] = sMO[roff + row0][col];
            a1[j] = sMO[roff + row1][col];
            b0[j] = sD2[roff + row0][col];
            b1[j] = sD2[roff + row1][col];
        }

        unsigned done0 = 0u, done1 = 0u;
        int   k0 = 0, k1 = 0;
        float d0 = 1.0f, d1 = 1.0f;
        int   dmask = 0, invtot = 0;

        #pragma unroll
        for (int k = 0; k < 8; k++) {
            // argmax over unpivoted rows of |a[k]|, row id in low 3 bits
            unsigned key0 = done0 ? 0u
                : ((__float_as_uint(fabsf(a0[k])) & 0xFFFFFFF8u) | (unsigned)row0);
            unsigned key1 = done1 ? 0u
                : ((__float_as_uint(fabsf(a1[k])) & 0xFFFFFFF8u) | (unsigned)row1);
            unsigned key = max(key0, key1);
            key = max(key, __shfl_xor_sync(0xffffffffu, key, 1));
            key = max(key, __shfl_xor_sync(0xffffffffu, key, 2));

            const int  pr   = (int)(key & 7u);   // pivot row
            const int  pa   = base + (pr >> 1);  // lane holding it
            const bool ps   = pr & 1;            // which register set
            const bool isP0 = (row0 == pr);
            const bool isP1 = (row1 == pr);

            // Broadcast pivot A row, live columns only (j < k are dead zeros)
            float pj[8];
            #pragma unroll
            for (int j = 0; j < 8; j++) {
                if (j >= k) {
                    const float s = ps ? a1[j] : a0[j];
                    pj[j] = __shfl_sync(0xffffffffu, s, pa);
                }
            }
            const float r  = frcp(pj[k]);
            const float m0 = isP0 ? 0.0f : a0[k] * r;
            const float m1 = isP1 ? 0.0f : a1[k] * r;

            if (isP0) { d0 = a0[k]; k0 = k; done0 = 1u; }
            if (isP1) { d1 = a1[k]; k1 = k; done1 = 1u; }

            #pragma unroll
            for (int j = 0; j < 8; j++) {
                if (j > k) {
                    a0[j] = fmaf(-m0, pj[j], a0[j]);
                    a1[j] = fmaf(-m1, pj[j], a1[j]);
                }
            }
            #pragma unroll
            for (int j = 0; j < 8; j++) {
                const float s = ps ? b1[j] : b0[j];
                const float q = __shfl_sync(0xffffffffu, s, pa);
                b0[j] = fmaf(-m0, q, b0[j]);
                b1[j] = fmaf(-m1, q, b1[j]);
            }

            // permutation sign: inversions added by appending pr (uniform in group)
            invtot += __popc((unsigned)dmask >> (pr + 1));
            dmask  |= 1 << pr;
        }

        // Trace contributions: Bhat[row][k_row] / d_row, one rcp for both rows
        float bv0 = b0[0];
        #pragma unroll
        for (int j = 1; j < 8; j++) bv0 = (k0 == j) ? b0[j] : bv0;
        float bv1 = b1[0];
        #pragma unroll
        for (int j = 1; j < 8; j++) bv1 = (k1 == j) ? b1[j] : bv1;

        const float dd = d0 * d1;
        float tr  = (bv0 * d1 + bv1 * d0) * frcp(dd);
        // sign applied exactly once per group (lane 0)
        float det = (ll == 0 && (invtot & 1)) ? -dd : dd;

        #pragma unroll
        for (int off = 1; off < 4; off <<= 1) {
            tr  += __shfl_xor_sync(0xffffffffu, tr,  off);
            det *= __shfl_xor_sync(0xffffffffu, det, off);
        }

        trsum   += tr;
        detprod *= det;
    }

    if (ll == 0) out[b * NCONF + c] = -0.5f * trsum * detprod;
}

extern "C" void kernel_launch(void* const* d_in, const int* in_sizes, int n_in,
                              void* d_out, int out_size)
{
    const float* MO     = (const float*)d_in[0];
    const float* d2MO   = (const float*)d_in[1];
    const int*   cfg_up = (const int*)d_in[2];
    const int*   cfg_dn = (const int*)d_in[3];
    float*       out    = (float*)d_out;

    kinetic_kernel<<<NBATCH, 256>>>(MO, d2MO, cfg_up, cfg_dn, out);
}

// round 3
// speedup vs baseline: 1.5731x; 1.1397x over previous
#include <cuda_runtime.h>

// Problem constants (fixed by the dataset)
#define NBATCH 8192
#define NEL    16      // NUP + NDOWN
#define NSP    8
#define NMO    32
#define NCONF  64

#define PIV_THRESH 2e-3f   // inputs are N(0,1); below this, redo with pivoting

__device__ __forceinline__ float frcp(float x) {
    float r;
    asm("rcp.approx.f32 %0, %1;" : "=f"(r) : "f"(x));
    return r;
}

// Block = one batch, 256 threads = 64 configs x 4 lanes; each lane holds
// rows 2*ll and 2*ll+1 of the two 8x8 systems (per spin).
//
// Fast path: Gauss-Jordan WITHOUT pivoting. Pivot row at step k is row k,
// so the owning lane (base + k/2) and register set (k&1) are compile-time:
// no argmax shuffles, no source selects, sign = +1, det = prod of pivots
// (known in every lane). Row ops applied to both A and B leave tr(A^-1 B)
// invariant; tr = sum_k Bfinal[k][k] / d_k.
//
// Safety: if any pivot magnitude in the warp drops below PIV_THRESH, the
// whole warp re-runs this spin with implicit partial pivoting (round-2
// algorithm) and overwrites its results. Rare for Gaussian data.
__global__ __launch_bounds__(256, 2)
void kinetic_kernel(const float* __restrict__ MO,
                    const float* __restrict__ d2MO,
                    const int*   __restrict__ cfg_up,
                    const int*   __restrict__ cfg_dn,
                    float*       __restrict__ out)
{
    __shared__ float sMO[NEL][NMO + 1];   // +1 pad: conflict-free column gathers
    __shared__ float sD2[NEL][NMO + 1];
    __shared__ int   sUp[NCONF * NSP];
    __shared__ int   sDn[NCONF * NSP];

    const int b   = blockIdx.x;
    const int tid = threadIdx.x;

    #pragma unroll
    for (int i = 0; i < 2; i++) {
        const int t = tid + i * 256;
        sMO[t >> 5][t & 31] = MO[b * NEL * NMO + t];
        sD2[t >> 5][t & 31] = d2MO[b * NEL * NMO + t];
        sUp[t] = cfg_up[t];
        sDn[t] = cfg_dn[t];
    }
    __syncthreads();

    const int c    = tid >> 2;      // config 0..63
    const int ll   = tid & 3;       // lane within 4-lane group
    const int lane = tid & 31;
    const int base = lane & 28;     // first lane of this group in the warp
    const int row0 = 2 * ll;
    const int row1 = 2 * ll + 1;

    float trsum   = 0.0f;
    float detprod = 1.0f;

    #pragma unroll 1
    for (int spin = 0; spin < 2; spin++) {
        const int* cfg  = spin ? (sDn + c * NSP) : (sUp + c * NSP);
        const int  roff = spin ? NSP : 0;

        // ---------------- fast path: no pivoting ----------------
        float a0[8], a1[8], b0[8], b1[8];
        #pragma unroll
        for (int j = 0; j < 8; j++) {
            const int col = cfg[j];
            a0[j] = sMO[roff + row0][col];
            a1[j] = sMO[roff + row1][col];
            b0[j] = sD2[roff + row0][col];
            b1[j] = sD2[roff + row1][col];
        }

        float det    = 1.0f;
        float minpiv = 1e30f;

        #pragma unroll
        for (int k = 0; k < 8; k++) {
            const int pa = base + (k >> 1);  // lane owning pivot row k

            // Broadcast pivot A row (live columns only) and full B row;
            // register set (k&1) is compile-time after unroll.
            float pj[8], q[8];
            #pragma unroll
            for (int j = k; j < 8; j++)
                pj[j] = __shfl_sync(0xffffffffu, (k & 1) ? a1[j] : a0[j], pa);
            #pragma unroll
            for (int j = 0; j < 8; j++)
                q[j]  = __shfl_sync(0xffffffffu, (k & 1) ? b1[j] : b0[j], pa);

            const float piv = pj[k];
            const float r   = frcp(piv);
            minpiv = fminf(minpiv, fabsf(piv));
            det   *= piv;

            float m0, m1;
            if (k & 1) {
                m0 = a0[k] * r;
                m1 = (ll == (k >> 1)) ? 0.0f : a1[k] * r;
            } else {
                m0 = (ll == (k >> 1)) ? 0.0f : a0[k] * r;
                m1 = a1[k] * r;
            }

            #pragma unroll
            for (int j = k + 1; j < 8; j++) {
                a0[j] = fmaf(-m0, pj[j], a0[j]);
                a1[j] = fmaf(-m1, pj[j], a1[j]);
            }
            #pragma unroll
            for (int j = 0; j < 8; j++) {
                b0[j] = fmaf(-m0, q[j], b0[j]);
                b1[j] = fmaf(-m1, q[j], b1[j]);
            }
        }

        // Diagonal pick: lane ll owns rows 2ll, 2ll+1.
        float d0 = a0[0], d1 = a1[1], bv0 = b0[0], bv1 = b1[1];
        if (ll == 1) { d0 = a0[2]; d1 = a1[3]; bv0 = b0[2]; bv1 = b1[3]; }
        if (ll == 2) { d0 = a0[4]; d1 = a1[5]; bv0 = b0[4]; bv1 = b1[5]; }
        if (ll == 3) { d0 = a0[6]; d1 = a1[7]; bv0 = b0[6]; bv1 = b1[7]; }

        float tr = (bv0 * d1 + bv1 * d0) * frcp(d0 * d1);
        tr += __shfl_xor_sync(0xffffffffu, tr, 1);
        tr += __shfl_xor_sync(0xffffffffu, tr, 2);
        // det already identical in all lanes of the group (sign = +1).

        // ------------- rare fallback: implicit partial pivoting -------------
        const bool bad = (minpiv < PIV_THRESH);
        if (__ballot_sync(0xffffffffu, bad)) {   // warp-uniform branch
            float c0[8], c1[8], e0[8], e1[8];
            #pragma unroll
            for (int j = 0; j < 8; j++) {
                const int col = cfg[j];
                c0[j] = sMO[roff + row0][col];
                c1[j] = sMO[roff + row1][col];
                e0[j] = sD2[roff + row0][col];
                e1[j] = sD2[roff + row1][col];
            }

            unsigned done0 = 0u, done1 = 0u;
            int   k0 = 0, k1 = 0;
            float p0 = 1.0f, p1 = 1.0f;
            int   dmask = 0, invtot = 0;

            #pragma unroll
            for (int k = 0; k < 8; k++) {
                unsigned key0 = done0 ? 0u
                    : ((__float_as_uint(fabsf(c0[k])) & 0xFFFFFFF8u) | (unsigned)row0);
                unsigned key1 = done1 ? 0u
                    : ((__float_as_uint(fabsf(c1[k])) & 0xFFFFFFF8u) | (unsigned)row1);
                unsigned key = max(key0, key1);
                key = max(key, __shfl_xor_sync(0xffffffffu, key, 1));
                key = max(key, __shfl_xor_sync(0xffffffffu, key, 2));

                const int  pr   = (int)(key & 7u);
                const int  pa   = base + (pr >> 1);
                const bool ps   = pr & 1;
                const bool isP0 = (row0 == pr);
                const bool isP1 = (row1 == pr);

                float pj[8];
                #pragma unroll
                for (int j = 0; j < 8; j++) {
                    if (j >= k) {
                        const float s = ps ? c1[j] : c0[j];
                        pj[j] = __shfl_sync(0xffffffffu, s, pa);
                    }
                }
                const float r  = frcp(pj[k]);
                const float m0 = isP0 ? 0.0f : c0[k] * r;
                const float m1 = isP1 ? 0.0f : c1[k] * r;

                if (isP0) { p0 = c0[k]; k0 = k; done0 = 1u; }
                if (isP1) { p1 = c1[k]; k1 = k; done1 = 1u; }

                #pragma unroll
                for (int j = 0; j < 8; j++) {
                    if (j > k) {
                        c0[j] = fmaf(-m0, pj[j], c0[j]);
                        c1[j] = fmaf(-m1, pj[j], c1[j]);
                    }
                }
                #pragma unroll
                for (int j = 0; j < 8; j++) {
                    const float s = ps ? e1[j] : e0[j];
                    const float q = __shfl_sync(0xffffffffu, s, pa);
                    e0[j] = fmaf(-m0, q, e0[j]);
                    e1[j] = fmaf(-m1, q, e1[j]);
                }

                invtot += __popc((unsigned)dmask >> (pr + 1));
                dmask  |= 1 << pr;
            }

            float bv0s = e0[0];
            #pragma unroll
            for (int j = 1; j < 8; j++) bv0s = (k0 == j) ? e0[j] : bv0s;
            float bv1s = e1[0];
            #pragma unroll
            for (int j = 1; j < 8; j++) bv1s = (k1 == j) ? e1[j] : bv1s;

            const float dd = p0 * p1;
            float trs  = (bv0s * p1 + bv1s * p0) * frcp(dd);
            float dets = (ll == 0 && (invtot & 1)) ? -dd : dd;

            #pragma unroll
            for (int off = 1; off < 4; off <<= 1) {
                trs  += __shfl_xor_sync(0xffffffffu, trs,  off);
                dets *= __shfl_xor_sync(0xffffffffu, dets, off);
            }

            tr  = trs;    // overwrite: pivoted results are correct for all groups
            det = dets;
        }

        trsum   += tr;
        detprod *= det;
    }

    if (ll == 0) out[b * NCONF + c] = -0.5f * trsum * detprod;
}

extern "C" void kernel_launch(void* const* d_in, const int* in_sizes, int n_in,
                              void* d_out, int out_size)
{
    const float* MO     = (const float*)d_in[0];
    const float* d2MO   = (const float*)d_in[1];
    const int*   cfg_up = (const int*)d_in[2];
    const int*   cfg_dn = (const int*)d_in[3];
    float*       out    = (float*)d_out;

    kinetic_kernel<<<NBATCH, 256>>>(MO, d2MO, cfg_up, cfg_dn, out);
}

// round 4
// speedup vs baseline: 1.5740x; 1.0005x over previous
#include <cuda_runtime.h>

// Problem constants (fixed by the dataset)
#define NBATCH 8192
#define NEL    16      // NUP + NDOWN
#define NSP    8
#define NMO    32
#define NCONF  64

#define PIV_THRESH 2e-3f   // inputs are N(0,1); below this, redo with pivoting

// Work list for groups needing the pivoted fallback (rare).
__device__ int g_count;
__device__ int g_list[NBATCH * NCONF];

__device__ __forceinline__ float frcp(float x) {
    float r;
    asm("rcp.approx.f32 %0, %1;" : "=f"(r) : "f"(x));
    return r;
}

__global__ void zero_count_kernel() { g_count = 0; }

// ---------------------------------------------------------------------------
// Fast kernel: block = one batch, 256 threads = 64 configs x 4 lanes; each
// lane holds rows 2*ll, 2*ll+1 of the two 8x8 systems (per spin).
// Gauss-Jordan WITHOUT pivoting: pivot row at step k is row k, so the owning
// lane and register set are compile-time; sign = +1, det = prod of pivots.
// Row ops applied to A and B leave tr(A^-1 B) invariant:
//   tr = sum_k Bfinal[k][k] / d_k.
// Groups with any |pivot| < PIV_THRESH are appended to g_list and fixed by
// the fallback kernel.
// ---------------------------------------------------------------------------
__global__ __launch_bounds__(256, 3)
void kinetic_fast_kernel(const float* __restrict__ MO,
                         const float* __restrict__ d2MO,
                         const int*   __restrict__ cfg_up,
                         const int*   __restrict__ cfg_dn,
                         float*       __restrict__ out)
{
    __shared__ float sMO[NEL][NMO + 1];   // +1 pad: conflict-free column gathers
    __shared__ float sD2[NEL][NMO + 1];
    __shared__ int   sUp[NCONF * NSP];
    __shared__ int   sDn[NCONF * NSP];

    const int b   = blockIdx.x;
    const int tid = threadIdx.x;

    #pragma unroll
    for (int i = 0; i < 2; i++) {
        const int t = tid + i * 256;
        sMO[t >> 5][t & 31] = MO[b * NEL * NMO + t];
        sD2[t >> 5][t & 31] = d2MO[b * NEL * NMO + t];
        sUp[t] = cfg_up[t];
        sDn[t] = cfg_dn[t];
    }
    __syncthreads();

    const int c    = tid >> 2;      // config 0..63
    const int ll   = tid & 3;       // lane within 4-lane group
    const int lane = tid & 31;
    const int base = lane & 28;     // first lane of this group in the warp
    const int row0 = 2 * ll;
    const int row1 = 2 * ll + 1;

    float trsum   = 0.0f;
    float detprod = 1.0f;
    bool  anybad  = false;

    #pragma unroll 1
    for (int spin = 0; spin < 2; spin++) {
        const int* cfg  = spin ? (sDn + c * NSP) : (sUp + c * NSP);
        const int  roff = spin ? NSP : 0;

        float a0[8], a1[8], b0[8], b1[8];
        #pragma unroll
        for (int j = 0; j < 8; j++) {
            const int col = cfg[j];
            a0[j] = sMO[roff + row0][col];
            a1[j] = sMO[roff + row1][col];
            b0[j] = sD2[roff + row0][col];
            b1[j] = sD2[roff + row1][col];
        }

        float det = 1.0f;

        #pragma unroll
        for (int k = 0; k < 8; k++) {
            const int pa = base + (k >> 1);  // lane owning pivot row k

            // Broadcast pivot A row (live cols only) and full B row;
            // register set (k&1) is compile-time after unroll.
            float pj[8], q[8];
            #pragma unroll
            for (int j = k; j < 8; j++)
                pj[j] = __shfl_sync(0xffffffffu, (k & 1) ? a1[j] : a0[j], pa);
            #pragma unroll
            for (int j = 0; j < 8; j++)
                q[j]  = __shfl_sync(0xffffffffu, (k & 1) ? b1[j] : b0[j], pa);

            const float piv = pj[k];
            const float r   = frcp(piv);
            anybad |= (fabsf(piv) < PIV_THRESH);
            det    *= piv;

            float m0, m1;
            if (k & 1) {
                m0 = a0[k] * r;
                m1 = (ll == (k >> 1)) ? 0.0f : a1[k] * r;
            } else {
                m0 = (ll == (k >> 1)) ? 0.0f : a0[k] * r;
                m1 = a1[k] * r;
            }

            #pragma unroll
            for (int j = k + 1; j < 8; j++) {
                a0[j] = fmaf(-m0, pj[j], a0[j]);
                a1[j] = fmaf(-m1, pj[j], a1[j]);
            }
            #pragma unroll
            for (int j = 0; j < 8; j++) {
                b0[j] = fmaf(-m0, q[j], b0[j]);
                b1[j] = fmaf(-m1, q[j], b1[j]);
            }
        }

        // Diagonal pick: lane ll owns rows 2ll, 2ll+1 (compile-time indices).
        float d0 = a0[0], d1 = a1[1], bv0 = b0[0], bv1 = b1[1];
        if (ll == 1) { d0 = a0[2]; d1 = a1[3]; bv0 = b0[2]; bv1 = b1[3]; }
        if (ll == 2) { d0 = a0[4]; d1 = a1[5]; bv0 = b0[4]; bv1 = b1[5]; }
        if (ll == 3) { d0 = a0[6]; d1 = a1[7]; bv0 = b0[6]; bv1 = b1[7]; }

        float tr = (bv0 * d1 + bv1 * d0) * frcp(d0 * d1);
        tr += __shfl_xor_sync(0xffffffffu, tr, 1);
        tr += __shfl_xor_sync(0xffffffffu, tr, 2);
        // det already identical in all lanes of the group (sign = +1).

        trsum   += tr;
        detprod *= det;
    }

    if (ll == 0) {
        out[b * NCONF + c] = -0.5f * trsum * detprod;
        if (anybad) {
            const int idx = atomicAdd(&g_count, 1);
            g_list[idx] = b * NCONF + c;
        }
    }
}

// ---------------------------------------------------------------------------
// Fallback: pivoted Gauss-Jordan (implicit partial pivoting, no row swaps)
// for the flagged groups. Same 4-lane/2-row layout; loads direct from global.
// ---------------------------------------------------------------------------
__global__ __launch_bounds__(256, 3)
void kinetic_fallback_kernel(const float* __restrict__ MO,
                             const float* __restrict__ d2MO,
                             const int*   __restrict__ cfg_up,
                             const int*   __restrict__ cfg_dn,
                             float*       __restrict__ out)
{
    const int count = g_count;
    if (count == 0) return;

    const int tid    = threadIdx.x;
    const int ll     = tid & 3;
    const int lane   = tid & 31;
    const int base   = lane & 28;
    const int row0   = 2 * ll;
    const int row1   = 2 * ll + 1;
    const int gBlk   = 64;                       // groups per block
    const int gTotal = gridDim.x * gBlk;

    for (int g0 = blockIdx.x * gBlk + (tid >> 2); g0 < ((count + gTotal - 1) / gTotal) * gTotal;
         g0 += gTotal)
    {
        const bool active = (g0 < count);
        const int  g   = active ? g0 : (count - 1);   // clamp: keep shuffles full-mask
        const int  id  = g_list[g];
        const int  b   = id >> 6;
        const int  c   = id & 63;

        float trsum = 0.0f, detprod = 1.0f;

        #pragma unroll 1
        for (int spin = 0; spin < 2; spin++) {
            const int* cfg  = (spin ? cfg_dn : cfg_up) + c * NSP;
            const int  roff = spin ? NSP : 0;
            const float* mo0 = MO   + (b * NEL + roff + row0) * NMO;
            const float* mo1 = MO   + (b * NEL + roff + row1) * NMO;
            const float* d20 = d2MO + (b * NEL + roff + row0) * NMO;
            const float* d21 = d2MO + (b * NEL + roff + row1) * NMO;

            float c0[8], c1[8], e0[8], e1[8];
            #pragma unroll
            for (int j = 0; j < 8; j++) {
                const int col = cfg[j];
                c0[j] = mo0[col];
                c1[j] = mo1[col];
                e0[j] = d20[col];
                e1[j] = d21[col];
            }

            unsigned done0 = 0u, done1 = 0u;
            int   k0 = 0, k1 = 0;
            float p0 = 1.0f, p1 = 1.0f;
            int   dmask = 0, invtot = 0;

            #pragma unroll
            for (int k = 0; k < 8; k++) {
                unsigned key0 = done0 ? 0u
                    : ((__float_as_uint(fabsf(c0[k])) & 0xFFFFFFF8u) | (unsigned)row0);
                unsigned key1 = done1 ? 0u
                    : ((__float_as_uint(fabsf(c1[k])) & 0xFFFFFFF8u) | (unsigned)row1);
                unsigned key = max(key0, key1);
                key = max(key, __shfl_xor_sync(0xffffffffu, key, 1));
                key = max(key, __shfl_xor_sync(0xffffffffu, key, 2));

                const int  pr   = (int)(key & 7u);
                const int  pa   = base + (pr >> 1);
                const bool ps   = pr & 1;
                const bool isP0 = (row0 == pr);
                const bool isP1 = (row1 == pr);

                float pj[8];
                #pragma unroll
                for (int j = 0; j < 8; j++) {
                    if (j >= k) {
                        const float s = ps ? c1[j] : c0[j];
                        pj[j] = __shfl_sync(0xffffffffu, s, pa);
                    }
                }
                const float r  = frcp(pj[k]);
                const float m0 = isP0 ? 0.0f : c0[k] * r;
                const float m1 = isP1 ? 0.0f : c1[k] * r;

                if (isP0) { p0 = c0[k]; k0 = k; done0 = 1u; }
                if (isP1) { p1 = c1[k]; k1 = k; done1 = 1u; }

                #pragma unroll
                for (int j = 0; j < 8; j++) {
                    if (j > k) {
                        c0[j] = fmaf(-m0, pj[j], c0[j]);
                        c1[j] = fmaf(-m1, pj[j], c1[j]);
                    }
                }
                #pragma unroll
                for (int j = 0; j < 8; j++) {
                    const float s = ps ? e1[j] : e0[j];
                    const float q = __shfl_sync(0xffffffffu, s, pa);
                    e0[j] = fmaf(-m0, q, e0[j]);
                    e1[j] = fmaf(-m1, q, e1[j]);
                }

                invtot += __popc((unsigned)dmask >> (pr + 1));
                dmask  |= 1 << pr;
            }

            float bv0 = e0[0];
            #pragma unroll
            for (int j = 1; j < 8; j++) bv0 = (k0 == j) ? e0[j] : bv0;
            float bv1 = e1[0];
            #pragma unroll
            for (int j = 1; j < 8; j++) bv1 = (k1 == j) ? e1[j] : bv1;

            const float dd = p0 * p1;
            float tr  = (bv0 * p1 + bv1 * p0) * frcp(dd);
            float det = (ll == 0 && (invtot & 1)) ? -dd : dd;

            #pragma unroll
            for (int off = 1; off < 4; off <<= 1) {
                tr  += __shfl_xor_sync(0xffffffffu, tr,  off);
                det *= __shfl_xor_sync(0xffffffffu, det, off);
            }

            trsum   += tr;
            detprod *= det;
        }

        if (active && ll == 0) out[id] = -0.5f * trsum * detprod;
    }
}

extern "C" void kernel_launch(void* const* d_in, const int* in_sizes, int n_in,
                              void* d_out, int out_size)
{
    const float* MO     = (const float*)d_in[0];
    const float* d2MO   = (const float*)d_in[1];
    const int*   cfg_up = (const int*)d_in[2];
    const int*   cfg_dn = (const int*)d_in[3];
    float*       out    = (float*)d_out;

    zero_count_kernel<<<1, 1>>>();
    kinetic_fast_kernel<<<NBATCH, 256>>>(MO, d2MO, cfg_up, cfg_dn, out);
    kinetic_fallback_kernel<<<512, 256>>>(MO, d2MO, cfg_up, cfg_dn, out);
}

// round 5
// speedup vs baseline: 1.8363x; 1.1666x over previous
#include <cuda_runtime.h>

// Problem constants (fixed by the dataset)
#define NBATCH 8192
#define NEL    16      // NUP + NDOWN
#define NSP    8
#define NMO    32
#define NCONF  64

#define PIV_THRESH 2e-3f   // inputs are N(0,1); below this, redo with pivoting

// Work list for groups needing the pivoted fallback (rare).
__device__ int      g_count;   // zero-initialized; fallback kernel re-zeros it
__device__ unsigned g_done;
__device__ int      g_list[NBATCH * NCONF];

__device__ __forceinline__ float frcp(float x) {
    float r;
    asm("rcp.approx.f32 %0, %1;" : "=f"(r) : "f"(x));
    return r;
}

// ---------------------------------------------------------------------------
// Fast kernel: block = one batch, 256 threads = 64 configs x 4 lanes; each
// lane holds rows 2*ll, 2*ll+1 of the two 8x8 systems (per spin).
//
// COLUMN-op Gauss-Jordan, no pivoting. Column ops preserve the trace:
//   tr((AF)^-1 (BF)) = tr(A^-1 B),  same F applied to A and B.
// Step k: multipliers m_j = A[k][j]/A[k][k] come from the pivot ROW only
// (one 8-value broadcast, shared by the A and B updates); every update
//   a[j] -= m_j * a[k],  b[j] -= m_j * b[k]
// is lane-local. A ends diagonal with A[k][k] = pivot_k; det = prod pivots;
// tr = sum_k Bfinal[k][k] / pivot_k.
// ---------------------------------------------------------------------------
__global__ __launch_bounds__(256, 4)
void kinetic_fast_kernel(const float* __restrict__ MO,
                         const float* __restrict__ d2MO,
                         const int*   __restrict__ cfg_up,
                         const int*   __restrict__ cfg_dn,
                         float*       __restrict__ out)
{
    __shared__ float sMO[NEL][NMO + 1];   // +1 pad: conflict-free column gathers
    __shared__ float sD2[NEL][NMO + 1];
    __shared__ int   sUp[NCONF * NSP];
    __shared__ int   sDn[NCONF * NSP];

    const int b   = blockIdx.x;
    const int tid = threadIdx.x;

    #pragma unroll
    for (int i = 0; i < 2; i++) {
        const int t = tid + i * 256;
        sMO[t >> 5][t & 31] = MO[b * NEL * NMO + t];
        sD2[t >> 5][t & 31] = d2MO[b * NEL * NMO + t];
        sUp[t] = cfg_up[t];
        sDn[t] = cfg_dn[t];
    }
    __syncthreads();

    const int c    = tid >> 2;      // config 0..63
    const int ll   = tid & 3;       // lane within 4-lane group
    const int lane = tid & 31;
    const int base = lane & 28;     // first lane of this group in the warp
    const int row0 = 2 * ll;
    const int row1 = 2 * ll + 1;

    float trsum   = 0.0f;
    float detprod = 1.0f;
    bool  anybad  = false;

    #pragma unroll 1
    for (int spin = 0; spin < 2; spin++) {
        const int* cfg  = spin ? (sDn + c * NSP) : (sUp + c * NSP);
        const int  roff = spin ? NSP : 0;

        float a0[8], a1[8], b0[8], b1[8];
        #pragma unroll
        for (int j = 0; j < 8; j++) {
            const int col = cfg[j];
            a0[j] = sMO[roff + row0][col];
            a1[j] = sMO[roff + row1][col];
            b0[j] = sD2[roff + row0][col];
            b1[j] = sD2[roff + row1][col];
        }

        float det = 1.0f;

        #pragma unroll
        for (int k = 0; k < 8; k++) {
            const int pa = base + (k >> 1);   // lane owning pivot row k

            // Broadcast pivot row of A; reg set (k&1) is compile-time.
            float pj[8];
            #pragma unroll
            for (int j = 0; j < 8; j++)
                pj[j] = __shfl_sync(0xffffffffu, (k & 1) ? a1[j] : a0[j], pa);

            const float piv = pj[k];
            const float r   = frcp(piv);
            anybad |= (fabsf(piv) < PIV_THRESH);
            det    *= piv;

            // Column updates: lane-local, same multipliers for A and B.
            #pragma unroll
            for (int j = 0; j < 8; j++) {
                if (j != k) {
                    const float m = pj[j] * r;
                    if (k < 7) {                       // A irrelevant after last step
                        a0[j] = fmaf(-m, a0[k], a0[j]);
                        a1[j] = fmaf(-m, a1[k], a1[j]);
                    }
                    b0[j] = fmaf(-m, b0[k], b0[j]);
                    b1[j] = fmaf(-m, b1[k], b1[j]);
                }
            }
        }

        // Epilogue: lane ll owns rows 2ll, 2ll+1. Final A diag = pivot values.
        float d0 = a0[0], d1 = a1[1], bv0 = b0[0], bv1 = b1[1];
        if (ll == 1) { d0 = a0[2]; d1 = a1[3]; bv0 = b0[2]; bv1 = b1[3]; }
        if (ll == 2) { d0 = a0[4]; d1 = a1[5]; bv0 = b0[4]; bv1 = b1[5]; }
        if (ll == 3) { d0 = a0[6]; d1 = a1[7]; bv0 = b0[6]; bv1 = b1[7]; }

        float tr = (bv0 * d1 + bv1 * d0) * frcp(d0 * d1);
        tr += __shfl_xor_sync(0xffffffffu, tr, 1);
        tr += __shfl_xor_sync(0xffffffffu, tr, 2);
        // det identical in all lanes of the group (sign = +1, no pivoting).

        trsum   += tr;
        detprod *= det;
    }

    if (ll == 0) {
        out[b * NCONF + c] = -0.5f * trsum * detprod;
        if (anybad) {
            const int idx = atomicAdd(&g_count, 1);
            g_list[idx] = b * NCONF + c;
        }
    }
}

// ---------------------------------------------------------------------------
// Fallback: ROW-op Gauss-Jordan with implicit partial pivoting (proven
// round-2/3 algorithm) for the flagged groups; loads direct from global.
// Last block to finish resets g_count/g_done for the next graph replay.
// ---------------------------------------------------------------------------
__global__ __launch_bounds__(256, 3)
void kinetic_fallback_kernel(const float* __restrict__ MO,
                             const float* __restrict__ d2MO,
                             const int*   __restrict__ cfg_up,
                             const int*   __restrict__ cfg_dn,
                             float*       __restrict__ out)
{
    const int count = g_count;
    if (count == 0) return;

    const int tid    = threadIdx.x;
    const int ll     = tid & 3;
    const int lane   = tid & 31;
    const int base   = lane & 28;
    const int row0   = 2 * ll;
    const int row1   = 2 * ll + 1;
    const int gBlk   = 64;                    // groups per block per pass
    const int gTotal = gridDim.x * gBlk;
    const int passes = (count + gTotal - 1) / gTotal;

    for (int p = 0; p < passes; p++) {
        const int  g0     = p * gTotal + blockIdx.x * gBlk + (tid >> 2);
        const bool active = (g0 < count);
        const int  g   = active ? g0 : (count - 1);   // clamp: keep shuffles full-mask
        const int  id  = g_list[g];
        const int  b   = id >> 6;
        const int  c   = id & 63;

        float trsum = 0.0f, detprod = 1.0f;

        #pragma unroll 1
        for (int spin = 0; spin < 2; spin++) {
            const int* cfg  = (spin ? cfg_dn : cfg_up) + c * NSP;
            const int  roff = spin ? NSP : 0;
            const float* mo0 = MO   + (b * NEL + roff + row0) * NMO;
            const float* mo1 = MO   + (b * NEL + roff + row1) * NMO;
            const float* d20 = d2MO + (b * NEL + roff + row0) * NMO;
            const float* d21 = d2MO + (b * NEL + roff + row1) * NMO;

            float c0[8], c1[8], e0[8], e1[8];
            #pragma unroll
            for (int j = 0; j < 8; j++) {
                const int col = cfg[j];
                c0[j] = mo0[col];
                c1[j] = mo1[col];
                e0[j] = d20[col];
                e1[j] = d21[col];
            }

            unsigned done0 = 0u, done1 = 0u;
            int   k0 = 0, k1 = 0;
            float p0 = 1.0f, p1 = 1.0f;
            int   dmask = 0, invtot = 0;

            #pragma unroll
            for (int k = 0; k < 8; k++) {
                unsigned key0 = done0 ? 0u
                    : ((__float_as_uint(fabsf(c0[k])) & 0xFFFFFFF8u) | (unsigned)row0);
                unsigned key1 = done1 ? 0u
                    : ((__float_as_uint(fabsf(c1[k])) & 0xFFFFFFF8u) | (unsigned)row1);
                unsigned key = max(key0, key1);
                key = max(key, __shfl_xor_sync(0xffffffffu, key, 1));
                key = max(key, __shfl_xor_sync(0xffffffffu, key, 2));

                const int  pr   = (int)(key & 7u);
                const int  pa   = base + (pr >> 1);
                const bool ps   = pr & 1;
                const bool isP0 = (row0 == pr);
                const bool isP1 = (row1 == pr);

                float pj[8];
                #pragma unroll
                for (int j = 0; j < 8; j++) {
                    if (j >= k) {
                        const float s = ps ? c1[j] : c0[j];
                        pj[j] = __shfl_sync(0xffffffffu, s, pa);
                    }
                }
                const float r  = frcp(pj[k]);
                const float m0 = isP0 ? 0.0f : c0[k] * r;
                const float m1 = isP1 ? 0.0f : c1[k] * r;

                if (isP0) { p0 = c0[k]; k0 = k; done0 = 1u; }
                if (isP1) { p1 = c1[k]; k1 = k; done1 = 1u; }

                #pragma unroll
                for (int j = 0; j < 8; j++) {
                    if (j > k) {
                        c0[j] = fmaf(-m0, pj[j], c0[j]);
                        c1[j] = fmaf(-m1, pj[j], c1[j]);
                    }
                }
                #pragma unroll
                for (int j = 0; j < 8; j++) {
                    const float s = ps ? e1[j] : e0[j];
                    const float q = __shfl_sync(0xffffffffu, s, pa);
                    e0[j] = fmaf(-m0, q, e0[j]);
                    e1[j] = fmaf(-m1, q, e1[j]);
                }

                invtot += __popc((unsigned)dmask >> (pr + 1));
                dmask  |= 1 << pr;
            }

            float bv0 = e0[0];
            #pragma unroll
            for (int j = 1; j < 8; j++) bv0 = (k0 == j) ? e0[j] : bv0;
            float bv1 = e1[0];
            #pragma unroll
            for (int j = 1; j < 8; j++) bv1 = (k1 == j) ? e1[j] : bv1;

            const float dd = p0 * p1;
            float tr  = (bv0 * p1 + bv1 * p0) * frcp(dd);
            float det = (ll == 0 && (invtot & 1)) ? -dd : dd;

            #pragma unroll
            for (int off = 1; off < 4; off <<= 1) {
                tr  += __shfl_xor_sync(0xffffffffu, tr,  off);
                det *= __shfl_xor_sync(0xffffffffu, det, off);
            }

            trsum   += tr;
            detprod *= det;
        }

        if (active && ll == 0) out[id] = -0.5f * trsum * detprod;
    }

    // Reset the work list for the next graph replay: last block to finish.
    __syncthreads();
    if (tid == 0) {
        __threadfence();
        const unsigned ticket = atomicAdd(&g_done, 1u);
        if (ticket == gridDim.x - 1) {
            g_count = 0;
            g_done  = 0;
            __threadfence();
        }
    }
}

extern "C" void kernel_launch(void* const* d_in, const int* in_sizes, int n_in,
                              void* d_out, int out_size)
{
    const float* MO     = (const float*)d_in[0];
    const float* d2MO   = (const float*)d_in[1];
    const int*   cfg_up = (const int*)d_in[2];
    const int*   cfg_dn = (const int*)d_in[3];
    float*       out    = (float*)d_out;

    kinetic_fast_kernel<<<NBATCH, 256>>>(MO, d2MO, cfg_up, cfg_dn, out);
    kinetic_fallback_kernel<<<256, 256>>>(MO, d2MO, cfg_up, cfg_dn, out);
}

// round 6
// speedup vs baseline: 1.9067x; 1.0384x over previous
#include <cuda_runtime.h>

// Problem constants (fixed by the dataset)
#define NBATCH 8192
#define NEL    16      // NUP + NDOWN
#define NSP    8
#define NMO    32
#define NCONF  64

// Inputs are N(0,1). Below this pivot magnitude, redo the group with
// pivoting. 5e-4 keeps elementwise error ~6e-5 (gate is 1e-3) while cutting
// the fallback population ~4x vs 2e-3.
#define PIV_THRESH 5e-4f

// Work list for groups needing the pivoted fallback (rare).
__device__ int      g_count;   // zero-initialized; fallback kernel re-zeros it
__device__ unsigned g_done;
__device__ int      g_list[NBATCH * NCONF];

__device__ __forceinline__ float frcp(float x) {
    float r;
    asm("rcp.approx.f32 %0, %1;" : "=f"(r) : "f"(x));
    return r;
}

// ---------------------------------------------------------------------------
// Fast kernel: block = one batch, 256 threads = 64 configs x 4 lanes; each
// lane holds rows 2*ll, 2*ll+1 of the two 8x8 systems (per spin).
//
// COLUMN-op Gauss-Jordan, no pivoting. Column ops preserve the trace:
//   tr((AF)^-1 (BF)) = tr(A^-1 B),  same F applied to A and B.
// Step k: multipliers m_j = A[k][j]/A[k][k] come from the pivot ROW only
// (one 8-value broadcast shared by A and B updates); every update
//   a[j] -= m_j * a[k],  b[j] -= m_j * b[k]
// is lane-local. A ends diagonal with A[k][k] = pivot_k; det = prod pivots;
// tr = sum_k Bfinal[k][k] / pivot_k.
// ---------------------------------------------------------------------------
__global__ __launch_bounds__(256, 4)
void kinetic_fast_kernel(const float* __restrict__ MO,
                         const float* __restrict__ d2MO,
                         const int*   __restrict__ cfg_up,
                         const int*   __restrict__ cfg_dn,
                         float*       __restrict__ out)
{
    __shared__ float sMO[NEL][NMO + 1];   // +1 pad: conflict-free column gathers
    __shared__ float sD2[NEL][NMO + 1];

    const int b   = blockIdx.x;
    const int tid = threadIdx.x;

    #pragma unroll
    for (int i = 0; i < 2; i++) {
        const int t = tid + i * 256;
        sMO[t >> 5][t & 31] = MO[b * NEL * NMO + t];
        sD2[t >> 5][t & 31] = d2MO[b * NEL * NMO + t];
    }
    __syncthreads();

    const int c    = tid >> 2;      // config 0..63
    const int ll   = tid & 3;       // lane within 4-lane group
    const int lane = tid & 31;
    const int base = lane & 28;     // first lane of this group in the warp
    const int row0 = 2 * ll;
    const int row1 = 2 * ll + 1;

    float trsum   = 0.0f;
    float detprod = 1.0f;
    bool  anybad  = false;

    #pragma unroll 1
    for (int spin = 0; spin < 2; spin++) {
        // Configs: 32B-aligned, tiny, L1/L2 resident across all 8192 blocks.
        const int4* cp = (const int4*)((spin ? cfg_dn : cfg_up) + c * NSP);
        const int4  cA = cp[0];
        const int4  cB = cp[1];
        const int   cfg[8] = { cA.x, cA.y, cA.z, cA.w, cB.x, cB.y, cB.z, cB.w };
        const int   roff = spin ? NSP : 0;

        float a0[8], a1[8], b0[8], b1[8];
        #pragma unroll
        for (int j = 0; j < 8; j++) {
            const int col = cfg[j];
            a0[j] = sMO[roff + row0][col];
            a1[j] = sMO[roff + row1][col];
            b0[j] = sD2[roff + row0][col];
            b1[j] = sD2[roff + row1][col];
        }

        float det = 1.0f;

        #pragma unroll
        for (int k = 0; k < 8; k++) {
            const int pa = base + (k >> 1);   // lane owning pivot row k

            // Broadcast pivot row of A; reg set (k&1) is compile-time.
            float pj[8];
            #pragma unroll
            for (int j = 0; j < 8; j++)
                pj[j] = __shfl_sync(0xffffffffu, (k & 1) ? a1[j] : a0[j], pa);

            const float piv = pj[k];
            const float r   = frcp(piv);
            anybad |= (fabsf(piv) < PIV_THRESH);
            det    *= piv;

            // Column updates: lane-local, same multipliers for A and B.
            #pragma unroll
            for (int j = 0; j < 8; j++) {
                if (j != k) {
                    const float m = pj[j] * r;
                    if (k < 7) {                       // A irrelevant after last step
                        a0[j] = fmaf(-m, a0[k], a0[j]);
                        a1[j] = fmaf(-m, a1[k], a1[j]);
                    }
                    b0[j] = fmaf(-m, b0[k], b0[j]);
                    b1[j] = fmaf(-m, b1[k], b1[j]);
                }
            }
        }

        // Epilogue: lane ll owns rows 2ll, 2ll+1. Final A diag = pivot values.
        float d0 = a0[0], d1 = a1[1], bv0 = b0[0], bv1 = b1[1];
        if (ll == 1) { d0 = a0[2]; d1 = a1[3]; bv0 = b0[2]; bv1 = b1[3]; }
        if (ll == 2) { d0 = a0[4]; d1 = a1[5]; bv0 = b0[4]; bv1 = b1[5]; }
        if (ll == 3) { d0 = a0[6]; d1 = a1[7]; bv0 = b0[6]; bv1 = b1[7]; }

        float tr = (bv0 * d1 + bv1 * d0) * frcp(d0 * d1);
        tr += __shfl_xor_sync(0xffffffffu, tr, 1);
        tr += __shfl_xor_sync(0xffffffffu, tr, 2);
        // det identical in all lanes of the group (sign = +1, no pivoting).

        trsum   += tr;
        detprod *= det;
    }

    if (ll == 0) {
        out[b * NCONF + c] = -0.5f * trsum * detprod;
        if (anybad) {
            const int idx = atomicAdd(&g_count, 1);
            g_list[idx] = b * NCONF + c;
        }
    }
}

// ---------------------------------------------------------------------------
// Fallback: ROW-op Gauss-Jordan with implicit partial pivoting (proven
// round-2/3 algorithm) for the flagged groups; loads direct from global.
// Last block to finish resets g_count/g_done for the next graph replay.
// ---------------------------------------------------------------------------
__global__ __launch_bounds__(256, 3)
void kinetic_fallback_kernel(const float* __restrict__ MO,
                             const float* __restrict__ d2MO,
                             const int*   __restrict__ cfg_up,
                             const int*   __restrict__ cfg_dn,
                             float*       __restrict__ out)
{
    const int count = g_count;
    if (count == 0) return;

    const int tid    = threadIdx.x;
    const int ll     = tid & 3;
    const int lane   = tid & 31;
    const int base   = lane & 28;
    const int row0   = 2 * ll;
    const int row1   = 2 * ll + 1;
    const int gBlk   = 64;                    // groups per block per pass
    const int gTotal = gridDim.x * gBlk;
    const int passes = (count + gTotal - 1) / gTotal;

    for (int p = 0; p < passes; p++) {
        const int  g0     = p * gTotal + blockIdx.x * gBlk + (tid >> 2);
        const bool active = (g0 < count);
        const int  g   = active ? g0 : (count - 1);   // clamp: keep shuffles full-mask
        const int  id  = g_list[g];
        const int  b   = id >> 6;
        const int  c   = id & 63;

        float trsum = 0.0f, detprod = 1.0f;

        #pragma unroll 1
        for (int spin = 0; spin < 2; spin++) {
            const int4* cp = (const int4*)((spin ? cfg_dn : cfg_up) + c * NSP);
            const int4  cAi = cp[0];
            const int4  cBi = cp[1];
            const int   cfg[8] = { cAi.x, cAi.y, cAi.z, cAi.w,
                                   cBi.x, cBi.y, cBi.z, cBi.w };
            const int  roff = spin ? NSP : 0;
            const float* mo0 = MO   + (b * NEL + roff + row0) * NMO;
            const float* mo1 = MO   + (b * NEL + roff + row1) * NMO;
            const float* d20 = d2MO + (b * NEL + roff + row0) * NMO;
            const float* d21 = d2MO + (b * NEL + roff + row1) * NMO;

            float c0[8], c1[8], e0[8], e1[8];
            #pragma unroll
            for (int j = 0; j < 8; j++) {
                const int col = cfg[j];
                c0[j] = mo0[col];
                c1[j] = mo1[col];
                e0[j] = d20[col];
                e1[j] = d21[col];
            }

            unsigned done0 = 0u, done1 = 0u;
            int   k0 = 0, k1 = 0;
            float p0 = 1.0f, p1 = 1.0f;
            int   dmask = 0, invtot = 0;

            #pragma unroll
            for (int k = 0; k < 8; k++) {
                unsigned key0 = done0 ? 0u
                    : ((__float_as_uint(fabsf(c0[k])) & 0xFFFFFFF8u) | (unsigned)row0);
                unsigned key1 = done1 ? 0u
                    : ((__float_as_uint(fabsf(c1[k])) & 0xFFFFFFF8u) | (unsigned)row1);
                unsigned key = max(key0, key1);
                key = max(key, __shfl_xor_sync(0xffffffffu, key, 1));
                key = max(key, __shfl_xor_sync(0xffffffffu, key, 2));

                const int  pr   = (int)(key & 7u);
                const int  pa   = base + (pr >> 1);
                const bool ps   = pr & 1;
                const bool isP0 = (row0 == pr);
                const bool isP1 = (row1 == pr);

                float pj[8];
                #pragma unroll
                for (int j = 0; j < 8; j++) {
                    if (j >= k) {
                        const float s = ps ? c1[j] : c0[j];
                        pj[j] = __shfl_sync(0xffffffffu, s, pa);
                    }
                }
                const float r  = frcp(pj[k]);
                const float m0 = isP0 ? 0.0f : c0[k] * r;
                const float m1 = isP1 ? 0.0f : c1[k] * r;

                if (isP0) { p0 = c0[k]; k0 = k; done0 = 1u; }
                if (isP1) { p1 = c1[k]; k1 = k; done1 = 1u; }

                #pragma unroll
                for (int j = 0; j < 8; j++) {
                    if (j > k) {
                        c0[j] = fmaf(-m0, pj[j], c0[j]);
                        c1[j] = fmaf(-m1, pj[j], c1[j]);
                    }
                }
                #pragma unroll
                for (int j = 0; j < 8; j++) {
                    const float s = ps ? e1[j] : e0[j];
                    const float q = __shfl_sync(0xffffffffu, s, pa);
                    e0[j] = fmaf(-m0, q, e0[j]);
                    e1[j] = fmaf(-m1, q, e1[j]);
                }

                invtot += __popc((unsigned)dmask >> (pr + 1));
                dmask  |= 1 << pr;
            }

            float bv0 = e0[0];
            #pragma unroll
            for (int j = 1; j < 8; j++) bv0 = (k0 == j) ? e0[j] : bv0;
            float bv1 = e1[0];
            #pragma unroll
            for (int j = 1; j < 8; j++) bv1 = (k1 == j) ? e1[j] : bv1;

            const float dd = p0 * p1;
            float tr  = (bv0 * p1 + bv1 * p0) * frcp(dd);
            float det = (ll == 0 && (invtot & 1)) ? -dd : dd;

            #pragma unroll
            for (int off = 1; off < 4; off <<= 1) {
                tr  += __shfl_xor_sync(0xffffffffu, tr,  off);
                det *= __shfl_xor_sync(0xffffffffu, det, off);
            }

            trsum   += tr;
            detprod *= det;
        }

        if (active && ll == 0) out[id] = -0.5f * trsum * detprod;
    }

    // Reset the work list for the next graph replay: last block to finish.
    __syncthreads();
    if (tid == 0) {
        __threadfence();
        const unsigned ticket = atomicAdd(&g_done, 1u);
        if (ticket == gridDim.x - 1) {
            g_count = 0;
            g_done  = 0;
            __threadfence();
        }
    }
}

extern "C" void kernel_launch(void* const* d_in, const int* in_sizes, int n_in,
                              void* d_out, int out_size)
{
    const float* MO     = (const float*)d_in[0];
    const float* d2MO   = (const float*)d_in[1];
    const int*   cfg_up = (const int*)d_in[2];
    const int*   cfg_dn = (const int*)d_in[3];
    float*       out    = (float*)d_out;

    kinetic_fast_kernel<<<NBATCH, 256>>>(MO, d2MO, cfg_up, cfg_dn, out);
    kinetic_fallback_kernel<<<256, 256>>>(MO, d2MO, cfg_up, cfg_dn, out);
}

// round 7
// speedup vs baseline: 3.4167x; 1.7919x over previous
#include <cuda_runtime.h>

typedef unsigned long long ull;

// Problem constants (fixed by the dataset)
#define NBATCH 8192
#define NEL    16      // NUP + NDOWN
#define NSP    8
#define NMO    32
#define NCONF  64

#define PIV_THRESH 2.5e-4f   // N(0,1) inputs; below this, redo with pivoting

#define BPB     2                 // batches per block (fast kernel)
#define THREADS (BPB * NCONF)     // 128
#define RPAD    20                // padded row-dim (NEL=16 -> 20, keeps 8B align)

// Work list for groups needing the pivoted fallback (rare).
__device__ int      g_count;   // zero-init; fallback kernel re-zeros it
__device__ unsigned g_done;
__device__ int      g_list[NBATCH * NCONF];

__device__ __forceinline__ float frcp(float x) {
    float r;
    asm("rcp.approx.f32 %0, %1;" : "=f"(r) : "f"(x));
    return r;
}

// f32x2 helpers: 64-bit carrier holds (lo=row 2p, hi=row 2p+1).
__device__ __forceinline__ ull pack2(float x) {
    ull r;
    asm("mov.b64 %0, {%1, %1};" : "=l"(r) : "r"(__float_as_uint(x)));
    return r;
}
__device__ __forceinline__ float lo2(ull v) {
    return __uint_as_float((unsigned)v);
}
__device__ __forceinline__ float hi2(ull v) {
    return __uint_as_float((unsigned)(v >> 32));
}
__device__ __forceinline__ ull ffma2(ull a, ull b, ull c) {   // a*b + c, packed
    ull d;
    asm("fma.rn.f32x2 %0, %1, %2, %3;" : "=l"(d) : "l"(a), "l"(b), "l"(c));
    return d;
}

// ---------------------------------------------------------------------------
// Fast kernel: ONE THREAD = ONE (batch, config) pair. Column-op Gauss-Jordan
// without pivoting; column ops preserve tr(A^-1 B) and det accumulates as the
// product of pivots. All indices compile-time; rows packed in pairs into
// 64-bit f32x2 registers so every column update is 4 FFMA2 for A + 4 for B
// with a single broadcast-free multiplier. Zero shuffles.
// SMEM holds the block's MO/d2MO slices TRANSPOSED (column-major) so one
// matrix column = 4 contiguous 8B words -> 4x LDS64.
// ---------------------------------------------------------------------------
__global__ __launch_bounds__(THREADS, 3)
void kinetic_fast_kernel(const float* __restrict__ MO,
                         const float* __restrict__ d2MO,
                         const int*   __restrict__ cfg_up,
                         const int*   __restrict__ cfg_dn,
                         float*       __restrict__ out)
{
    __shared__ float sMO[BPB][NMO][RPAD];   // [batch][mo-col][electron-row]
    __shared__ float sD2[BPB][NMO][RPAD];

    const int tid = threadIdx.x;
    const int b0  = blockIdx.x * BPB;

    // Stage + transpose: 1024 elements per array, 8 per thread, coalesced reads.
    #pragma unroll
    for (int i = 0; i < (BPB * NEL * NMO) / THREADS; i++) {
        const int e   = tid + i * THREADS;
        const int bl  = e >> 9;          // /512
        const int rem = e & 511;
        const int row = rem >> 5;        // electron 0..15
        const int col = rem & 31;        // MO 0..31
        sMO[bl][col][row] = MO[(b0 + bl) * NEL * NMO + rem];
        sD2[bl][col][row] = d2MO[(b0 + bl) * NEL * NMO + rem];
    }
    __syncthreads();

    const int bl = tid >> 6;   // batch within block
    const int c  = tid & 63;   // config

    float trsum   = 0.0f;
    float detprod = 1.0f;
    bool  anybad  = false;

    #pragma unroll 1
    for (int spin = 0; spin < 2; spin++) {
        const int4* cp = (const int4*)((spin ? cfg_dn : cfg_up) + c * NSP);
        const int4  cA = cp[0];
        const int4  cB = cp[1];
        const int   cfg[8] = { cA.x, cA.y, cA.z, cA.w, cB.x, cB.y, cB.z, cB.w };
        const int   roff = spin ? NSP : 0;

        // A, B: 8 columns x 4 packed row-pairs each.
        ull A[8][4], Bm[8][4];
        #pragma unroll
        for (int j = 0; j < 8; j++) {
            const ull* pa = (const ull*)&sMO[bl][cfg[j]][roff];
            const ull* pb = (const ull*)&sD2[bl][cfg[j]][roff];
            #pragma unroll
            for (int p = 0; p < 4; p++) { A[j][p] = pa[p]; Bm[j][p] = pb[p]; }
        }

        float det = 1.0f;

        #pragma unroll
        for (int k = 0; k < 8; k++) {
            // Pivot = row k of column k; row k of column j gives multiplier m_j.
            const float piv = (k & 1) ? hi2(A[k][k >> 1]) : lo2(A[k][k >> 1]);
            const float nr  = -frcp(piv);
            anybad |= (fabsf(piv) < PIV_THRESH);
            det    *= piv;

            #pragma unroll
            for (int j = 0; j < 8; j++) {
                if (j == k) continue;
                const float akj = (k & 1) ? hi2(A[j][k >> 1]) : lo2(A[j][k >> 1]);
                const ull   nm  = pack2(akj * nr);   // (-m_j, -m_j)
                if (k < 7) {                          // A irrelevant after step 7
                    #pragma unroll
                    for (int p = 0; p < 4; p++)
                        A[j][p] = ffma2(nm, A[k][p], A[j][p]);
                }
                #pragma unroll
                for (int p = 0; p < 4; p++)
                    Bm[j][p] = ffma2(nm, Bm[k][p], Bm[j][p]);
            }
        }

        // Trace: A is (numerically) diagonal with A[k][k] = pivot_k.
        float tr = 0.0f;
        #pragma unroll
        for (int k = 0; k < 8; k++) {
            const float dk = (k & 1) ? hi2(A[k][k >> 1])  : lo2(A[k][k >> 1]);
            const float bk = (k & 1) ? hi2(Bm[k][k >> 1]) : lo2(Bm[k][k >> 1]);
            tr = fmaf(bk, frcp(dk), tr);
        }

        trsum   += tr;
        detprod *= det;
    }

    const int id = (b0 + bl) * NCONF + c;
    out[id] = -0.5f * trsum * detprod;
    if (anybad) {
        const int idx = atomicAdd(&g_count, 1);
        g_list[idx] = id;
    }
}

// ---------------------------------------------------------------------------
// Fallback: ROW-op Gauss-Jordan with implicit partial pivoting (proven
// round-2/3 algorithm; 4 lanes per group) for the flagged groups; loads
// direct from global. Last block resets g_count/g_done for graph replay.
// ---------------------------------------------------------------------------
__global__ __launch_bounds__(256, 3)
void kinetic_fallback_kernel(const float* __restrict__ MO,
                             const float* __restrict__ d2MO,
                             const int*   __restrict__ cfg_up,
                             const int*   __restrict__ cfg_dn,
                             float*       __restrict__ out)
{
    const int count = g_count;
    if (count > 0) {

    const int tid    = threadIdx.x;
    const int ll     = tid & 3;
    const int lane   = tid & 31;
    const int base   = lane & 28;
    const int row0   = 2 * ll;
    const int row1   = 2 * ll + 1;
    const int gBlk   = 64;                    // groups per block per pass
    const int gTotal = gridDim.x * gBlk;
    const int passes = (count + gTotal - 1) / gTotal;

    for (int p = 0; p < passes; p++) {
        const int  g0     = p * gTotal + blockIdx.x * gBlk + (tid >> 2);
        const bool active = (g0 < count);
        const int  g   = active ? g0 : (count - 1);   // clamp: full-mask shuffles
        const int  id  = g_list[g];
        const int  b   = id >> 6;
        const int  c   = id & 63;

        float trsum = 0.0f, detprod = 1.0f;

        #pragma unroll 1
        for (int spin = 0; spin < 2; spin++) {
            const int4* cp = (const int4*)((spin ? cfg_dn : cfg_up) + c * NSP);
            const int4  cAi = cp[0];
            const int4  cBi = cp[1];
            const int   cfg[8] = { cAi.x, cAi.y, cAi.z, cAi.w,
                                   cBi.x, cBi.y, cBi.z, cBi.w };
            const int  roff = spin ? NSP : 0;
            const float* mo0 = MO   + (b * NEL + roff + row0) * NMO;
            const float* mo1 = MO   + (b * NEL + roff + row1) * NMO;
            const float* d20 = d2MO + (b * NEL + roff + row0) * NMO;
            const float* d21 = d2MO + (b * NEL + roff + row1) * NMO;

            float c0[8], c1[8], e0[8], e1[8];
            #pragma unroll
            for (int j = 0; j < 8; j++) {
                const int col = cfg[j];
                c0[j] = mo0[col];
                c1[j] = mo1[col];
                e0[j] = d20[col];
                e1[j] = d21[col];
            }

            unsigned done0 = 0u, done1 = 0u;
            int   k0 = 0, k1 = 0;
            float p0 = 1.0f, p1 = 1.0f;
            int   dmask = 0, invtot = 0;

            #pragma unroll
            for (int k = 0; k < 8; k++) {
                unsigned key0 = done0 ? 0u
                    : ((__float_as_uint(fabsf(c0[k])) & 0xFFFFFFF8u) | (unsigned)row0);
                unsigned key1 = done1 ? 0u
                    : ((__float_as_uint(fabsf(c1[k])) & 0xFFFFFFF8u) | (unsigned)row1);
                unsigned key = max(key0, key1);
                key = max(key, __shfl_xor_sync(0xffffffffu, key, 1));
                key = max(key, __shfl_xor_sync(0xffffffffu, key, 2));

                const int  pr   = (int)(key & 7u);
                const int  pa   = base + (pr >> 1);
                const bool ps   = pr & 1;
                const bool isP0 = (row0 == pr);
                const bool isP1 = (row1 == pr);

                float pj[8];
                #pragma unroll
                for (int j = 0; j < 8; j++) {
                    if (j >= k) {
                        const float s = ps ? c1[j] : c0[j];
                        pj[j] = __shfl_sync(0xffffffffu, s, pa);
                    }
                }
                const float r  = frcp(pj[k]);
                const float m0 = isP0 ? 0.0f : c0[k] * r;
                const float m1 = isP1 ? 0.0f : c1[k] * r;

                if (isP0) { p0 = c0[k]; k0 = k; done0 = 1u; }
                if (isP1) { p1 = c1[k]; k1 = k; done1 = 1u; }

                #pragma unroll
                for (int j = 0; j < 8; j++) {
                    if (j > k) {
                        c0[j] = fmaf(-m0, pj[j], c0[j]);
                        c1[j] = fmaf(-m1, pj[j], c1[j]);
                    }
                }
                #pragma unroll
                for (int j = 0; j < 8; j++) {
                    const float s = ps ? e1[j] : e0[j];
                    const float q = __shfl_sync(0xffffffffu, s, pa);
                    e0[j] = fmaf(-m0, q, e0[j]);
                    e1[j] = fmaf(-m1, q, e1[j]);
                }

                invtot += __popc((unsigned)dmask >> (pr + 1));
                dmask  |= 1 << pr;
            }

            float bv0 = e0[0];
            #pragma unroll
            for (int j = 1; j < 8; j++) bv0 = (k0 == j) ? e0[j] : bv0;
            float bv1 = e1[0];
            #pragma unroll
            for (int j = 1; j < 8; j++) bv1 = (k1 == j) ? e1[j] : bv1;

            const float dd = p0 * p1;
            float tr  = (bv0 * p1 + bv1 * p0) * frcp(dd);
            float det = (ll == 0 && (invtot & 1)) ? -dd : dd;

            #pragma unroll
            for (int off = 1; off < 4; off <<= 1) {
                tr  += __shfl_xor_sync(0xffffffffu, tr,  off);
                det *= __shfl_xor_sync(0xffffffffu, det, off);
            }

            trsum   += tr;
            detprod *= det;
        }

        if (active && ll == 0) out[id] = -0.5f * trsum * detprod;
    }

    }  // count > 0

    // Reset the work list for the next graph replay: last block to finish.
    __syncthreads();
    if (threadIdx.x == 0) {
        __threadfence();
        const unsigned ticket = atomicAdd(&g_done, 1u);
        if (ticket == gridDim.x - 1) {
            g_count = 0;
            g_done  = 0;
            __threadfence();
        }
    }
}

extern "C" void kernel_launch(void* const* d_in, const int* in_sizes, int n_in,
                              void* d_out, int out_size)
{
    const float* MO     = (const float*)d_in[0];
    const float* d2MO   = (const float*)d_in[1];
    const int*   cfg_up = (const int*)d_in[2];
    const int*   cfg_dn = (const int*)d_in[3];
    float*       out    = (float*)d_out;

    kinetic_fast_kernel<<<NBATCH / BPB, THREADS>>>(MO, d2MO, cfg_up, cfg_dn, out);
    kinetic_fallback_kernel<<<64, 256>>>(MO, d2MO, cfg_up, cfg_dn, out);
}